// round 1
// baseline (speedup 1.0000x reference)
#include <cuda_runtime.h>
#include <math.h>

#define BB 4
#define NN 20000
#define MM 1024
#define CAP 1024
#define KSEL 50

// scratch (device globals — allocation-free)
__device__ int   g_count[BB*MM];
__device__ int   g_p2n[BB*NN];
__device__ float g_tp[BB*NN*3];
__device__ int   g_bidx[BB*MM*CAP];
__device__ float g_bdist[BB*MM*CAP];
__device__ float g_l1[BB*MM];

__global__ void k_zero() {
    int i = blockIdx.x * blockDim.x + threadIdx.x;
    if (i < BB*MM) g_count[i] = 0;
}

// Kernel 1: per-point nearest keypoint (brute force over M=1024 in smem),
// transform point by pose, scatter (idx,dist) into per-node bucket.
__global__ void k_assign(const float* __restrict__ pts,
                         const float* __restrict__ kp,
                         const float* __restrict__ pose) {
    __shared__ float4 skp[MM];
    const int b = blockIdx.y;
    const float* kpb = kp + (size_t)b * MM * 3;
    for (int i = threadIdx.x; i < MM; i += blockDim.x) {
        float x = kpb[3*i+0], y = kpb[3*i+1], z = kpb[3*i+2];
        skp[i] = make_float4(x, y, z, x*x + y*y + z*z);
    }
    __syncthreads();

    const int n = blockIdx.x * blockDim.x + threadIdx.x;
    if (n >= NN) return;

    const float* p = pts + ((size_t)b * NN + n) * 3;
    const float px = p[0], py = p[1], pz = p[2];
    const float psq = px*px + py*py + pz*pz;

    float best = 3.4e38f;
    int   bi   = 0;
    #pragma unroll 8
    for (int m = 0; m < MM; m++) {
        float4 k4 = skp[m];
        float d = k4.x * px;
        d = fmaf(k4.y, py, d);
        d = fmaf(k4.z, pz, d);
        float s = fmaf(-2.0f, d, k4.w);   // |kp|^2 - 2*dot  (psq is constant per point)
        if (s < best) { best = s; bi = m; }
    }
    const float dist = best + psq;        // full sq_dist value for rank among node's points

    g_p2n[b*NN + n] = bi;
    int pos = atomicAdd(&g_count[b*MM + bi], 1);
    if (pos < CAP) {
        g_bidx [(size_t)(b*MM + bi) * CAP + pos] = n;
        g_bdist[(size_t)(b*MM + bi) * CAP + pos] = dist;
    }

    // tp = R * p + t  (pose row-major 4x4)
    const float* P = pose + b * 16;
    float tx = fmaf(P[0],  px, fmaf(P[1],  py, fmaf(P[2],  pz, P[3])));
    float ty = fmaf(P[4],  px, fmaf(P[5],  py, fmaf(P[6],  pz, P[7])));
    float tz = fmaf(P[8],  px, fmaf(P[9],  py, fmaf(P[10], pz, P[11])));
    float* t = g_tp + ((size_t)b * NN + n) * 3;
    t[0] = tx; t[1] = ty; t[2] = tz;
}

// Kernel 2: one thread per node. Deterministic canonical-order sums.
__global__ void k_select(const float* __restrict__ kpw) {
    const int id = blockIdx.x * blockDim.x + threadIdx.x;
    if (id >= BB*MM) return;
    const int b = id / MM;
    const int m = id % MM;

    const int c  = g_count[id];
    const int cc = min(c, CAP);
    const int*   bidx  = &g_bidx [(size_t)id * CAP];
    const float* bdist = &g_bdist[(size_t)id * CAP];

    float sx = 0.f, sy = 0.f, sz = 0.f;

    if (c <= KSEL) {
        // all assigned points, ascending point index (canonical order)
        int last = -1;
        for (int r = 0; r < cc; r++) {
            int mn = 0x7fffffff;
            for (int j = 0; j < cc; j++) {
                int v = bidx[j];
                if (v > last && v < mn) mn = v;
            }
            last = mn;
            const float* t = &g_tp[((size_t)b * NN + mn) * 3];
            sx += t[0]; sy += t[1]; sz += t[2];
        }
        // pad with the smallest indices NOT assigned to this node
        int k = KSEL - c;
        const int* p2n = &g_p2n[b * NN];
        int n = 0;
        while (k > 0) {
            if (p2n[n] != m) {
                const float* t = &g_tp[((size_t)b * NN + n) * 3];
                sx += t[0]; sy += t[1]; sz += t[2];
                k--;
            }
            n++;
        }
    } else {
        // rare: true 50 smallest by (dist, idx), extracted in order (deterministic)
        float lastd = -3.4e38f; int lasti = -1;
        for (int r = 0; r < KSEL; r++) {
            float bd = 3.4e38f; int bsel = 0x7fffffff;
            for (int j = 0; j < cc; j++) {
                float d = bdist[j];
                int   i = bidx[j];
                bool gt = (d > lastd) || (d == lastd && i > lasti);
                bool lt = (d < bd)    || (d == bd    && i < bsel);
                if (gt && lt) { bd = d; bsel = i; }
            }
            lastd = bd; lasti = bsel;
            const float* t = &g_tp[((size_t)b * NN + bsel) * 3];
            sx += t[0]; sy += t[1]; sz += t[2];
        }
    }

    const float inv = 1.0f / (float)KSEL;
    const float* kw = kpw + (size_t)id * 3;
    float ex = sx * inv - kw[0];
    float ey = sy * inv - kw[1];
    float ez = sz * inv - kw[2];
    g_l1[id] = fabsf(ex) + fabsf(ey) + fabsf(ez);
}

// Kernel 3: deterministic weighted-mean reduction over B*M nodes.
__global__ void k_reduce(const float* __restrict__ ow, float* __restrict__ out) {
    __shared__ float snum[256];
    __shared__ float sden[256];
    float num = 0.f, den = 0.f;
    for (int i = threadIdx.x; i < BB*MM; i += 256) {
        float w = ow[i];
        num = fmaf(w, g_l1[i], num);
        den += w;
    }
    snum[threadIdx.x] = num;
    sden[threadIdx.x] = den;
    __syncthreads();
    for (int s = 128; s > 0; s >>= 1) {
        if (threadIdx.x < s) {
            snum[threadIdx.x] += snum[threadIdx.x + s];
            sden[threadIdx.x] += sden[threadIdx.x + s];
        }
        __syncthreads();
    }
    if (threadIdx.x == 0) out[0] = snum[0] / fmaxf(sden[0], 1e-6f);
}

extern "C" void kernel_launch(void* const* d_in, const int* in_sizes, int n_in,
                              void* d_out, int out_size) {
    const float* pts  = (const float*)d_in[0];  // (B,N,3)
    const float* kp   = (const float*)d_in[1];  // (B,M,3)
    const float* kpw  = (const float*)d_in[2];  // (B,M,3)
    const float* pose = (const float*)d_in[3];  // (B,4,4)
    const float* ow   = (const float*)d_in[4];  // (B,M)
    float* out = (float*)d_out;

    k_zero<<<(BB*MM + 255) / 256, 256>>>();

    dim3 g1((NN + 255) / 256, BB);
    k_assign<<<g1, 256>>>(pts, kp, pose);

    k_select<<<(BB*MM + 255) / 256, 256>>>(kpw);

    k_reduce<<<1, 256>>>(ow, out);
}

// round 6
// speedup vs baseline: 2.5425x; 2.5425x over previous
#include <cuda_runtime.h>
#include <math.h>

#define BB 4
#define NN 20000
#define MM 1024
#define CAP 1024
#define KSEL 50
#define PPT 4   // points per thread in k_assign

// scratch (device globals — allocation-free)
__device__ int    g_count[BB*MM];
__device__ int    g_p2n[BB*NN];
__device__ float4 g_tp4[(BB*NN*3)/4];      // transformed points, float4-aligned
__device__ int    g_bidx[BB*MM*CAP];
__device__ float  g_bdist[BB*MM*CAP];
__device__ float  g_l1[BB*MM];

__global__ void k_zero() {
    int i = blockIdx.x * blockDim.x + threadIdx.x;
    if (i < BB*MM) g_count[i] = 0;
}

// ---------------------------------------------------------------------------
// Kernel 1: per-point nearest keypoint. 4 points/thread, keypoints in smem as
// (-2x, -2y, -2z, |kp|^2) so the inner body is 3 FMAs per (point,kp) pair.
// Also transforms each point by the GT pose and scatters (idx, dist) into the
// per-node bucket.
// ---------------------------------------------------------------------------
__global__ void k_assign(const float* __restrict__ pts,
                         const float* __restrict__ kp,
                         const float* __restrict__ pose) {
    __shared__ float4 skp[MM];
    const int b = blockIdx.y;
    const float* kpb = kp + (size_t)b * MM * 3;
    for (int i = threadIdx.x; i < MM; i += blockDim.x) {
        float x = kpb[3*i+0], y = kpb[3*i+1], z = kpb[3*i+2];
        skp[i] = make_float4(-2.f*x, -2.f*y, -2.f*z, x*x + y*y + z*z);
    }
    __syncthreads();

    const int t  = blockIdx.x * blockDim.x + threadIdx.x;
    const int n0 = t * PPT;
    if (n0 >= NN) return;     // NN % PPT == 0 -> all-or-nothing per thread

    // load 4 consecutive points = 12 floats = 3 float4 (48B aligned)
    const float4* pv = (const float4*)(pts + ((size_t)b * NN + n0) * 3);
    float4 A = pv[0], B = pv[1], C = pv[2];
    float px[PPT] = {A.x, A.w, B.z, C.y};
    float py[PPT] = {A.y, B.x, B.w, C.z};
    float pz[PPT] = {A.z, B.y, C.x, C.w};

    float best[PPT]; int bi[PPT];
    #pragma unroll
    for (int j = 0; j < PPT; j++) { best[j] = 3.4e38f; bi[j] = 0; }

    #pragma unroll 4
    for (int m = 0; m < MM; m++) {
        float4 k4 = skp[m];
        #pragma unroll
        for (int j = 0; j < PPT; j++) {
            float s = fmaf(k4.z, pz[j], fmaf(k4.y, py[j], fmaf(k4.x, px[j], k4.w)));
            if (s < best[j]) { best[j] = s; bi[j] = m; }
        }
    }

    const float* P = pose + b * 16;
    float R00=P[0],R01=P[1],R02=P[2],T0=P[3];
    float R10=P[4],R11=P[5],R12=P[6],T1=P[7];
    float R20=P[8],R21=P[9],R22=P[10],T2=P[11];

    float tp[12];
    #pragma unroll
    for (int j = 0; j < PPT; j++) {
        const int n = n0 + j;
        float psq = fmaf(px[j],px[j], fmaf(py[j],py[j], pz[j]*pz[j]));
        float dist = best[j] + psq;   // == full sq_dist to its nearest node

        g_p2n[b*NN + n] = bi[j];
        int pos = atomicAdd(&g_count[b*MM + bi[j]], 1);
        if (pos < CAP) {
            g_bidx [(size_t)(b*MM + bi[j]) * CAP + pos] = n;
            g_bdist[(size_t)(b*MM + bi[j]) * CAP + pos] = dist;
        }
        tp[3*j+0] = fmaf(R00,px[j], fmaf(R01,py[j], fmaf(R02,pz[j], T0)));
        tp[3*j+1] = fmaf(R10,px[j], fmaf(R11,py[j], fmaf(R12,pz[j], T1)));
        tp[3*j+2] = fmaf(R20,px[j], fmaf(R21,py[j], fmaf(R22,pz[j], T2)));
    }
    float4* tv = g_tp4 + ((size_t)b * NN + n0) * 3 / 4;
    tv[0] = make_float4(tp[0],tp[1],tp[2],tp[3]);
    tv[1] = make_float4(tp[4],tp[5],tp[6],tp[7]);
    tv[2] = make_float4(tp[8],tp[9],tp[10],tp[11]);
}

// orderable packing of (dist, idx) for lexicographic min via u64
__device__ __forceinline__ unsigned long long packdi(float d, int i) {
    unsigned int b = __float_as_uint(d);
    b = (b & 0x80000000u) ? ~b : (b | 0x80000000u);
    return ((unsigned long long)b << 32) | (unsigned int)i;
}

// ---------------------------------------------------------------------------
// Kernel 2: ONE WARP PER NODE. All sums computed in a fixed deterministic
// order that does not depend on the (nondeterministic) bucket slot order:
// entries are extracted by a total order (index asc, or (dist,idx) asc).
// ---------------------------------------------------------------------------
__global__ void k_select(const float* __restrict__ kpw) {
    const int gw   = (blockIdx.x * blockDim.x + threadIdx.x) >> 5;  // node id
    const int lane = threadIdx.x & 31;
    const int id = gw;
    const int b  = id >> 10;
    const int m  = id & (MM - 1);

    const int c  = g_count[id];
    const int cc = min(c, CAP);
    const int*   bidx  = &g_bidx [(size_t)id * CAP];
    const float* bdist = &g_bdist[(size_t)id * CAP];
    const float* tpf   = (const float*)g_tp4 + (size_t)b * NN * 3;

    float sx = 0.f, sy = 0.f, sz = 0.f;   // identical on every lane

    if (c <= KSEL) {
        // --- assigned points, extracted in ascending index order ---
        int v0 = (lane      < cc) ? bidx[lane]      : 0x7fffffff;
        int v1 = (lane + 32 < cc) ? bidx[lane + 32] : 0x7fffffff;
        int last = -1;
        for (int r = 0; r < cc; r++) {
            int a0 = (v0 > last) ? v0 : 0x7fffffff;
            int a1 = (v1 > last) ? v1 : 0x7fffffff;
            int mn = min(a0, a1);
            #pragma unroll
            for (int off = 16; off > 0; off >>= 1)
                mn = min(mn, __shfl_xor_sync(0xffffffffu, mn, off));
            last = mn;
            const float* t = tpf + (size_t)mn * 3;
            sx += t[0]; sy += t[1]; sz += t[2];
        }
        // --- pad with smallest UNassigned indices (ballot scan) ---
        int k = KSEL - c;
        const int* p2n = &g_p2n[b * NN];
        int n0 = 0;
        while (k > 0) {
            int n = n0 + lane;
            int pm = (n < NN) ? p2n[n] : m;   // OOB treated as assigned -> excluded
            bool un = (pm != m);
            unsigned mask = __ballot_sync(0xffffffffu, un);
            int cnt  = __popc(mask);
            int take = min(k, cnt);
            int rank = __popc(mask & ((1u << lane) - 1u));
            bool sel = un && (rank < take);
            float tx = 0.f, ty = 0.f, tz = 0.f;
            if (sel) {
                const float* t = tpf + (size_t)n * 3;
                tx = t[0]; ty = t[1]; tz = t[2];
            }
            #pragma unroll
            for (int off = 16; off > 0; off >>= 1) {
                tx += __shfl_xor_sync(0xffffffffu, tx, off);
                ty += __shfl_xor_sync(0xffffffffu, ty, off);
                tz += __shfl_xor_sync(0xffffffffu, tz, off);
            }
            sx += tx; sy += ty; sz += tz;
            k -= take;
            n0 += 32;
        }
    } else {
        // --- rare: 50 smallest by (dist, idx), extracted in that order ---
        unsigned long long last = 0ull;
        for (int r = 0; r < KSEL; r++) {
            unsigned long long mn = 0xffffffffffffffffull;
            for (int base = 0; base < cc; base += 32) {
                int j = base + lane;
                unsigned long long key = (j < cc) ? packdi(bdist[j], bidx[j])
                                                  : 0xffffffffffffffffull;
                if (key <= last) key = 0xffffffffffffffffull;
                mn = min(mn, key);
            }
            #pragma unroll
            for (int off = 16; off > 0; off >>= 1) {
                unsigned long long o = __shfl_xor_sync(0xffffffffu, mn, off);
                mn = min(mn, o);
            }
            last = mn;
            int selN = (int)(mn & 0xffffffffu);
            const float* t = tpf + (size_t)selN * 3;
            sx += t[0]; sy += t[1]; sz += t[2];
        }
    }

    if (lane == 0) {
        const float inv = 1.0f / (float)KSEL;
        const float* kw = kpw + (size_t)id * 3;
        float ex = sx * inv - kw[0];
        float ey = sy * inv - kw[1];
        float ez = sz * inv - kw[2];
        g_l1[id] = fabsf(ex) + fabsf(ey) + fabsf(ez);
    }
}

// Kernel 3: deterministic weighted-mean reduction over B*M nodes.
__global__ void k_reduce(const float* __restrict__ ow, float* __restrict__ out) {
    __shared__ float snum[256];
    __shared__ float sden[256];
    float num = 0.f, den = 0.f;
    for (int i = threadIdx.x; i < BB*MM; i += 256) {
        float w = ow[i];
        num = fmaf(w, g_l1[i], num);
        den += w;
    }
    snum[threadIdx.x] = num;
    sden[threadIdx.x] = den;
    __syncthreads();
    for (int s = 128; s > 0; s >>= 1) {
        if (threadIdx.x < s) {
            snum[threadIdx.x] += snum[threadIdx.x + s];
            sden[threadIdx.x] += sden[threadIdx.x + s];
        }
        __syncthreads();
    }
    if (threadIdx.x == 0) out[0] = snum[0] / fmaxf(sden[0], 1e-6f);
}

extern "C" void kernel_launch(void* const* d_in, const int* in_sizes, int n_in,
                              void* d_out, int out_size) {
    const float* pts  = (const float*)d_in[0];  // (B,N,3)
    const float* kp   = (const float*)d_in[1];  // (B,M,3)
    const float* kpw  = (const float*)d_in[2];  // (B,M,3)
    const float* pose = (const float*)d_in[3];  // (B,4,4)
    const float* ow   = (const float*)d_in[4];  // (B,M)
    float* out = (float*)d_out;

    k_zero<<<(BB*MM + 255) / 256, 256>>>();

    dim3 g1((NN/PPT + 255) / 256, BB);
    k_assign<<<g1, 256>>>(pts, kp, pose);

    k_select<<<(BB*MM) / 8, 256>>>(kpw);   // 8 warps/block, 1 warp per node

    k_reduce<<<1, 256>>>(ow, out);
}

// round 7
// speedup vs baseline: 2.9456x; 1.1585x over previous
#include <cuda_runtime.h>
#include <math.h>

#define BB 4
#define NN 20000
#define MM 1024
#define CAP 1024
#define KSEL 50
#define PPT 2            // points per thread in k_assign
#define SEL_BLOCKS 512   // k_select blocks (8 warps = 8 nodes each)

typedef unsigned long long ull;

// scratch (device globals — allocation-free). BSS zero at process start;
// k_final re-zeros g_count at the end of every launch (invariant).
__device__ int    g_count[BB*MM];
__device__ int    g_p2n[BB*NN];
__device__ float  g_tp[BB*NN*3];
__device__ int    g_bidx[BB*MM*CAP];
__device__ float  g_bdist[BB*MM*CAP];
__device__ long long g_pnum[SEL_BLOCKS];
__device__ long long g_pden[SEL_BLOCKS];

__device__ __forceinline__ ull f2fma(ull a, ull b, ull c) {
    ull d;
    asm("fma.rn.f32x2 %0, %1, %2, %3;" : "=l"(d) : "l"(a), "l"(b), "l"(c));
    return d;
}
__device__ __forceinline__ ull packf2(float lo, float hi) {
    ull d;
    asm("mov.b64 %0, {%1, %2};" : "=l"(d) : "f"(lo), "f"(hi));
    return d;
}

// ---------------------------------------------------------------------------
// Kernel 1: per-point nearest keypoint, 2 points/thread with packed f32x2 FMA.
// smem holds keypoints pre-duplicated: sA[m]=(-2x,-2x,-2y,-2y),
// sB[m]=(-2z,-2z,ss,ss) so the inner body is 3 FFMA2 for 2 points, no packing.
// Fused: pose transform + bucket scatter.
// ---------------------------------------------------------------------------
__global__ void __launch_bounds__(128) k_assign(const float* __restrict__ pts,
                                                const float* __restrict__ kp,
                                                const float* __restrict__ pose) {
    __shared__ float4 sA[MM];
    __shared__ float4 sB[MM];
    const int b = blockIdx.y;
    const float* kpb = kp + (size_t)b * MM * 3;
    for (int i = threadIdx.x; i < MM; i += blockDim.x) {
        float x = kpb[3*i+0], y = kpb[3*i+1], z = kpb[3*i+2];
        float ss = x*x + y*y + z*z;
        sA[i] = make_float4(-2.f*x, -2.f*x, -2.f*y, -2.f*y);
        sB[i] = make_float4(-2.f*z, -2.f*z, ss, ss);
    }
    __syncthreads();

    const int t  = blockIdx.x * blockDim.x + threadIdx.x;
    const int n0 = t * PPT;
    if (n0 >= NN) return;   // NN even -> pair all-or-nothing

    const float* p = pts + ((size_t)b * NN + n0) * 3;
    const float2 q0 = ((const float2*)p)[0];   // x0 y0
    const float2 q1 = ((const float2*)p)[1];   // z0 x1
    const float2 q2 = ((const float2*)p)[2];   // y1 z1
    const float px0 = q0.x, py0 = q0.y, pz0 = q1.x;
    const float px1 = q1.y, py1 = q2.x, pz1 = q2.y;

    const ull px2 = packf2(px0, px1);
    const ull py2 = packf2(py0, py1);
    const ull pz2 = packf2(pz0, pz1);

    const ulonglong2* __restrict__ A2 = (const ulonglong2*)sA;
    const ulonglong2* __restrict__ B2 = (const ulonglong2*)sB;

    float best0 = 3.4e38f, best1 = 3.4e38f;
    int   bi0 = 0, bi1 = 0;

    #pragma unroll 4
    for (int m = 0; m < MM; m++) {
        ulonglong2 a = A2[m];        // (kx2, ky2)
        ulonglong2 c = B2[m];        // (kz2, kw2)
        ull acc = f2fma(a.x, px2, c.y);
        acc = f2fma(a.y, py2, acc);
        acc = f2fma(c.x, pz2, acc);
        float s0 = __uint_as_float((unsigned)acc);
        float s1 = __uint_as_float((unsigned)(acc >> 32));
        if (s0 < best0) { best0 = s0; bi0 = m; }
        if (s1 < best1) { best1 = s1; bi1 = m; }
    }

    const float* P = pose + b * 16;
    float R00=P[0],R01=P[1],R02=P[2],T0=P[3];
    float R10=P[4],R11=P[5],R12=P[6],T1=P[7];
    float R20=P[8],R21=P[9],R22=P[10],T2=P[11];

    // point 0
    {
        float psq = fmaf(px0,px0, fmaf(py0,py0, pz0*pz0));
        float dist = best0 + psq;
        g_p2n[b*NN + n0] = bi0;
        int pos = atomicAdd(&g_count[b*MM + bi0], 1);
        if (pos < CAP) {
            g_bidx [(size_t)(b*MM + bi0) * CAP + pos] = n0;
            g_bdist[(size_t)(b*MM + bi0) * CAP + pos] = dist;
        }
    }
    // point 1
    {
        float psq = fmaf(px1,px1, fmaf(py1,py1, pz1*pz1));
        float dist = best1 + psq;
        g_p2n[b*NN + n0 + 1] = bi1;
        int pos = atomicAdd(&g_count[b*MM + bi1], 1);
        if (pos < CAP) {
            g_bidx [(size_t)(b*MM + bi1) * CAP + pos] = n0 + 1;
            g_bdist[(size_t)(b*MM + bi1) * CAP + pos] = dist;
        }
    }

    float t0x = fmaf(R00,px0, fmaf(R01,py0, fmaf(R02,pz0, T0)));
    float t0y = fmaf(R10,px0, fmaf(R11,py0, fmaf(R12,pz0, T1)));
    float t0z = fmaf(R20,px0, fmaf(R21,py0, fmaf(R22,pz0, T2)));
    float t1x = fmaf(R00,px1, fmaf(R01,py1, fmaf(R02,pz1, T0)));
    float t1y = fmaf(R10,px1, fmaf(R11,py1, fmaf(R12,pz1, T1)));
    float t1z = fmaf(R20,px1, fmaf(R21,py1, fmaf(R22,pz1, T2)));
    float2* tv = (float2*)(g_tp + ((size_t)b * NN + n0) * 3);
    tv[0] = make_float2(t0x, t0y);
    tv[1] = make_float2(t0z, t1x);
    tv[2] = make_float2(t1y, t1z);
}

// orderable packing of (dist, idx) for lexicographic min via u64
__device__ __forceinline__ ull packdi(float d, int i) {
    unsigned int b = __float_as_uint(d);
    b = (b & 0x80000000u) ? ~b : (b | 0x80000000u);
    return ((ull)b << 32) | (unsigned int)i;
}

// ---------------------------------------------------------------------------
// Kernel 2: ONE WARP PER NODE (8 nodes/block). Fast path sorts the bucket's
// indices with a 64-wide warp bitonic sort (canonical order => deterministic
// despite nondeterministic bucket slot order). Per-block integer fixed-point
// partial sums (order-free) go to g_pnum/g_pden.
// ---------------------------------------------------------------------------
__global__ void __launch_bounds__(256) k_select(const float* __restrict__ kpw,
                                                const float* __restrict__ ow) {
    __shared__ long long s_num[8];
    __shared__ long long s_den[8];

    const int warp = threadIdx.x >> 5;
    const int lane = threadIdx.x & 31;
    const int id   = blockIdx.x * 8 + warp;     // node id, exactly BB*MM of them
    const int b    = id >> 10;
    const int m    = id & (MM - 1);

    const int c  = g_count[id];
    const int cc = min(c, CAP);
    const int*   bidx  = &g_bidx [(size_t)id * CAP];
    const float* bdist = &g_bdist[(size_t)id * CAP];
    const float* tpf   = g_tp + (size_t)b * NN * 3;

    float sx = 0.f, sy = 0.f, sz = 0.f;   // identical on every lane

    if (c <= KSEL) {
        // ---- bitonic sort of 64 index keys (INT_MAX padded), ascending ----
        int v0 = (lane      < cc) ? bidx[lane]      : 0x7fffffff;
        int v1 = (lane + 32 < cc) ? bidx[lane + 32] : 0x7fffffff;
        #pragma unroll
        for (int k = 2; k <= 32; k <<= 1) {
            #pragma unroll
            for (int j = k >> 1; j >= 1; j >>= 1) {
                bool up0 = ((lane & k) == 0);
                bool up1 = (((lane + 32) & k) == 0);
                bool low = ((lane & j) == 0);
                int o0 = __shfl_xor_sync(0xffffffffu, v0, j);
                int o1 = __shfl_xor_sync(0xffffffffu, v1, j);
                v0 = (low == up0) ? min(v0, o0) : max(v0, o0);
                v1 = (low == up1) ? min(v1, o1) : max(v1, o1);
            }
        }
        { // k = 64 merge: j=32 is the local exchange, then j=16..1 (all ascending)
            int lo_ = min(v0, v1), hi_ = max(v0, v1); v0 = lo_; v1 = hi_;
            #pragma unroll
            for (int j = 16; j >= 1; j >>= 1) {
                bool low = ((lane & j) == 0);
                int o0 = __shfl_xor_sync(0xffffffffu, v0, j);
                int o1 = __shfl_xor_sync(0xffffffffu, v1, j);
                v0 = low ? min(v0, o0) : max(v0, o0);
                v1 = low ? min(v1, o1) : max(v1, o1);
            }
        }
        // gather + one butterfly reduce (canonical content => deterministic)
        float ax = 0.f, ay = 0.f, az = 0.f;
        if (lane < cc) {
            const float* tt = tpf + (size_t)v0 * 3;
            ax += tt[0]; ay += tt[1]; az += tt[2];
        }
        if (lane + 32 < cc) {
            const float* tt = tpf + (size_t)v1 * 3;
            ax += tt[0]; ay += tt[1]; az += tt[2];
        }
        #pragma unroll
        for (int off = 16; off > 0; off >>= 1) {
            ax += __shfl_xor_sync(0xffffffffu, ax, off);
            ay += __shfl_xor_sync(0xffffffffu, ay, off);
            az += __shfl_xor_sync(0xffffffffu, az, off);
        }
        sx += ax; sy += ay; sz += az;

        // ---- pad with smallest UNassigned indices (ballot scan) ----
        int k = KSEL - c;
        const int* p2n = &g_p2n[b * NN];
        int n0 = 0;
        while (k > 0) {
            int n = n0 + lane;
            int pm = (n < NN) ? p2n[n] : m;
            bool un = (pm != m);
            unsigned mask = __ballot_sync(0xffffffffu, un);
            int cnt  = __popc(mask);
            int take = min(k, cnt);
            int rank = __popc(mask & ((1u << lane) - 1u));
            bool sel = un && (rank < take);
            float tx = 0.f, ty = 0.f, tz = 0.f;
            if (sel) {
                const float* tt = tpf + (size_t)n * 3;
                tx = tt[0]; ty = tt[1]; tz = tt[2];
            }
            #pragma unroll
            for (int off = 16; off > 0; off >>= 1) {
                tx += __shfl_xor_sync(0xffffffffu, tx, off);
                ty += __shfl_xor_sync(0xffffffffu, ty, off);
                tz += __shfl_xor_sync(0xffffffffu, tz, off);
            }
            sx += tx; sy += ty; sz += tz;
            k -= take;
            n0 += 32;
        }
    } else {
        // rare: 50 smallest by (dist, idx), extracted in that order
        ull last = 0ull;
        for (int r = 0; r < KSEL; r++) {
            ull mn = 0xffffffffffffffffull;
            for (int base = 0; base < cc; base += 32) {
                int j = base + lane;
                ull key = (j < cc) ? packdi(bdist[j], bidx[j])
                                   : 0xffffffffffffffffull;
                if (key <= last) key = 0xffffffffffffffffull;
                mn = min(mn, key);
            }
            #pragma unroll
            for (int off = 16; off > 0; off >>= 1) {
                ull o = __shfl_xor_sync(0xffffffffu, mn, off);
                mn = min(mn, o);
            }
            last = mn;
            int selN = (int)(mn & 0xffffffffu);
            const float* tt = tpf + (size_t)selN * 3;
            sx += tt[0]; sy += tt[1]; sz += tt[2];
        }
    }

    if (lane == 0) {
        const float inv = 1.0f / (float)KSEL;
        const float* kw = kpw + (size_t)id * 3;
        float ex = sx * inv - kw[0];
        float ey = sy * inv - kw[1];
        float ez = sz * inv - kw[2];
        float l1 = fabsf(ex) + fabsf(ey) + fabsf(ez);
        double w = (double)ow[id];
        // Q32 fixed point: integer sums are order-free => deterministic
        s_num[warp] = (long long)(w * (double)l1 * 4294967296.0);
        s_den[warp] = (long long)(w * 4294967296.0);
    }
    __syncthreads();
    if (threadIdx.x == 0) {
        long long n = 0, d = 0;
        #pragma unroll
        for (int i = 0; i < 8; i++) { n += s_num[i]; d += s_den[i]; }
        g_pnum[blockIdx.x] = n;
        g_pden[blockIdx.x] = d;
    }
}

// ---------------------------------------------------------------------------
// Kernel 3: final integer reduce + divide; also re-zeros g_count so the
// next launch (or graph replay) starts from the required zero state.
// ---------------------------------------------------------------------------
__global__ void __launch_bounds__(256) k_final(float* __restrict__ out) {
    __shared__ long long rn[256];
    __shared__ long long rd[256];
    const int t = threadIdx.x;
    long long n = g_pnum[t] + g_pnum[t + 256];
    long long d = g_pden[t] + g_pden[t + 256];
    rn[t] = n; rd[t] = d;
    __syncthreads();
    for (int s = 128; s > 0; s >>= 1) {
        if (t < s) { rn[t] += rn[t + s]; rd[t] += rd[t + s]; }
        __syncthreads();
    }
    if (t == 0) {
        double num = (double)rn[0] * (1.0 / 4294967296.0);
        double den = (double)rd[0] * (1.0 / 4294967296.0);
        out[0] = (float)(num / fmax(den, 1e-6));
    }
    // restore invariant: counts zero for next launch
    for (int i = t; i < BB*MM; i += 256) g_count[i] = 0;
}

extern "C" void kernel_launch(void* const* d_in, const int* in_sizes, int n_in,
                              void* d_out, int out_size) {
    const float* pts  = (const float*)d_in[0];  // (B,N,3)
    const float* kp   = (const float*)d_in[1];  // (B,M,3)
    const float* kpw  = (const float*)d_in[2];  // (B,M,3)
    const float* pose = (const float*)d_in[3];  // (B,4,4)
    const float* ow   = (const float*)d_in[4];  // (B,M)
    float* out = (float*)d_out;

    dim3 g1((NN/PPT + 127) / 128, BB);
    k_assign<<<g1, 128>>>(pts, kp, pose);

    k_select<<<SEL_BLOCKS, 256>>>(kpw, ow);

    k_final<<<1, 256>>>(out);
}